// round 5
// baseline (speedup 1.0000x reference)
#include <cuda_runtime.h>
#include <cstdint>
#include <cstddef>

// x_{t+1} = x_t + 0.1*tanh([x_t,u_t]@W1 + b1)@W2 + b2
// B=1024, T=200, SD=64, CD=32, H=512.
// 128 persistent CTAs x 512 threads; 8 batch rows per CTA packed as 4 f32x2
// row-pairs. Phase A: thread owns one H-column; W1 32k in regs + 64k streamed.
// Phase B: 16-way k-split x i-pair; h row-paired, W2 scalar dup'd.

typedef unsigned long long u64;

static constexpr int   TSTEPS = 200;
static constexpr int   SDIM   = 64;
static constexpr int   CDIM   = 32;
static constexpr int   INDIM  = 96;
static constexpr int   HDIM   = 512;
static constexpr int   ROWS   = 8;
static constexpr int   NBLK   = 1024 / ROWS;   // 128
static constexpr int   NTHR   = 512;
static constexpr float DTC    = 0.1f;

static constexpr int W2_U = HDIM * SDIM / 2;  // 16384 u64 (W2 raw, pairs along i)
static constexpr int H_U  = HDIM * 4;         //  2048 u64: h[k][rp] row-paired
static constexpr int IN_U = INDIM * 4;        //   384 u64: in[k][rp] row-paired
static constexpr int PS_U = 16 * 4 * SDIM;    //  4096 u64: psd[ks][rp][i]
static constexpr size_t SMEM_BYTES =
    (size_t)(W2_U + H_U + IN_U + PS_U) * 8 + (size_t)SDIM * 4;  // 183,552 B

__device__ __forceinline__ u64 ffma2(u64 a, u64 b, u64 c) {
    u64 d;
    asm("fma.rn.f32x2 %0, %1, %2, %3;" : "=l"(d) : "l"(a), "l"(b), "l"(c));
    return d;
}
__device__ __forceinline__ u64 fadd2(u64 a, u64 b) {
    u64 d;
    asm("add.rn.f32x2 %0, %1, %2;" : "=l"(d) : "l"(a), "l"(b));
    return d;
}
__device__ __forceinline__ u64 pack2(float lo, float hi) {
    u64 d;
    asm("mov.b64 %0, {%1, %2};" : "=l"(d) : "r"(__float_as_int(lo)), "r"(__float_as_int(hi)));
    return d;
}
__device__ __forceinline__ u64 dupf(float f) {
    u64 d;
    asm("mov.b64 %0, {%1, %1};" : "=l"(d) : "r"(__float_as_int(f)));
    return d;
}
__device__ __forceinline__ float2 unpack2(u64 d) {
    int lo, hi;
    asm("mov.b64 {%0, %1}, %2;" : "=r"(lo), "=r"(hi) : "l"(d));
    return make_float2(__int_as_float(lo), __int_as_float(hi));
}
__device__ __forceinline__ float fast_tanh(float x) {
    float e = __expf(2.0f * x);
    return 1.0f - __fdividef(2.0f, e + 1.0f);
}

__global__ void __launch_bounds__(NTHR, 1)
rollout_kernel(const float* __restrict__ x0,
               const float* __restrict__ controls,
               const float* __restrict__ W1,
               const float* __restrict__ b1,
               const float* __restrict__ W2,
               const float* __restrict__ b2,
               float* __restrict__ out)
{
    extern __shared__ u64 sm[];
    u64*   W2p = sm;              // [k][32] pairs {W2[k][2i], W2[k][2i+1]}
    u64*   h_d = W2p + W2_U;      // [k][rp] {h_r(2rp), h_r(2rp+1)}
    u64*   in_s = h_d + H_U;      // [k][rp] row-paired inputs
    u64*   psd = in_s + IN_U;     // [ks][rp][i]
    float* b2s = (float*)(psd + PS_U);

    const int tid  = threadIdx.x;
    const int lane = tid & 31;
    const int b0   = blockIdx.x * ROWS;
    const int ks   = tid >> 5;          // phase B k-strip 0..15 (32 k each)
    const int rpE  = tid >> 6;          // epilogue rp (tid<256): 0..3
    const int iE   = tid & 63;          // epilogue col
    const int rpU  = tid >> 5;          // u-staging rp (tid<128)

    // ---- prologue ----
    {
        const float4* src = (const float4*)W2;
        float4* dst = (float4*)W2p;
        #pragma unroll
        for (int i = tid; i < (HDIM * SDIM) / 4; i += NTHR) dst[i] = src[i];
    }
    if (tid < SDIM) b2s[tid] = b2[tid];

    const u64 b1dup = dupf(b1[tid]);   // column c = tid

    // stage x0 (row-paired), u(0); emit states[:,0,:]
    if (tid < 256) {
        const int rp = rpE, d = iE;
        float a = x0[(b0 + 2 * rp) * SDIM + d];
        float b = x0[(b0 + 2 * rp + 1) * SDIM + d];
        in_s[d * 4 + rp] = pack2(a, b);
    }
    if (tid < 128) {
        const int rp = rpU, j = lane;
        float a = controls[(size_t)(b0 + 2 * rp) * TSTEPS * CDIM + j];
        float b = controls[(size_t)(b0 + 2 * rp + 1) * TSTEPS * CDIM + j];
        in_s[(SDIM + j) * 4 + rp] = pack2(a, b);
    }
    {
        const int r = tid >> 6, d = tid & 63;
        out[(size_t)(b0 + r) * (TSTEPS + 1) * SDIM + d] = x0[(b0 + r) * SDIM + d];
    }

    // persistent W1 k=0..31 for column tid
    float wper[32];
    #pragma unroll
    for (int kk = 0; kk < 32; ++kk) wper[kk] = W1[kk * HDIM + tid];
    // streamed W1 double buffer (k=32..95, 4 blocks of 16)
    float wbuf[2][16];
    #pragma unroll
    for (int kk = 0; kk < 16; ++kk) wbuf[0][kk] = W1[(32 + kk) * HDIM + tid];

    __syncthreads();

    for (int t = 0; t < TSTEPS; ++t) {
        // prefetch next-step controls (row pair) early
        float un0 = 0.0f, un1 = 0.0f;
        if (tid < 128 && t + 1 < TSTEPS) {
            un0 = controls[(size_t)(b0 + 2 * rpU) * TSTEPS * CDIM
                           + (size_t)(t + 1) * CDIM + lane];
            un1 = controls[(size_t)(b0 + 2 * rpU + 1) * TSTEPS * CDIM
                           + (size_t)(t + 1) * CDIM + lane];
        }

        // ---- Phase A: acc[rp] += in[k][rp] * {w,w}; one column per thread ----
        u64 acc0 = b1dup, acc1 = b1dup, acc2 = b1dup, acc3 = b1dup;
        #pragma unroll
        for (int kk = 0; kk < 32; ++kk) {
            ulonglong2 uA = *(const ulonglong2*)&in_s[kk * 4];
            ulonglong2 uB = *(const ulonglong2*)&in_s[kk * 4 + 2];
            u64 w = dupf(wper[kk]);
            acc0 = ffma2(uA.x, w, acc0);
            acc1 = ffma2(uA.y, w, acc1);
            acc2 = ffma2(uB.x, w, acc2);
            acc3 = ffma2(uB.y, w, acc3);
        }
        #pragma unroll
        for (int blk = 0; blk < 4; ++blk) {
            const int cur = blk & 1;
            const int knext = (blk < 3) ? (48 + 16 * blk) : 32;
            #pragma unroll
            for (int kk = 0; kk < 16; ++kk)
                wbuf[cur ^ 1][kk] = W1[(knext + kk) * HDIM + tid];
            #pragma unroll
            for (int kk = 0; kk < 16; ++kk) {
                const int k = 32 + blk * 16 + kk;
                ulonglong2 uA = *(const ulonglong2*)&in_s[k * 4];
                ulonglong2 uB = *(const ulonglong2*)&in_s[k * 4 + 2];
                u64 w = dupf(wbuf[cur][kk]);
                acc0 = ffma2(uA.x, w, acc0);
                acc1 = ffma2(uA.y, w, acc1);
                acc2 = ffma2(uB.x, w, acc2);
                acc3 = ffma2(uB.y, w, acc3);
            }
        }
        {   // tanh + row-paired store: h[k=tid][rp]
            float2 a0 = unpack2(acc0), a1 = unpack2(acc1);
            float2 a2 = unpack2(acc2), a3 = unpack2(acc3);
            u64 h0 = pack2(fast_tanh(a0.x), fast_tanh(a0.y));
            u64 h1 = pack2(fast_tanh(a1.x), fast_tanh(a1.y));
            u64 h2 = pack2(fast_tanh(a2.x), fast_tanh(a2.y));
            u64 h3 = pack2(fast_tanh(a3.x), fast_tanh(a3.y));
            *(ulonglong2*)&h_d[tid * 4]     = make_ulonglong2(h0, h1);
            *(ulonglong2*)&h_d[tid * 4 + 2] = make_ulonglong2(h2, h3);
        }
        __syncthreads();

        // ---- Phase B: acc[rp][i0/i1] += h[k][rp] * {w_i, w_i} ----
        u64 B00 = 0, B01 = 0, B10 = 0, B11 = 0, B20 = 0, B21 = 0, B30 = 0, B31 = 0;
        #pragma unroll 8
        for (int q = 0; q < 32; ++q) {
            const int k = ks * 32 + q;
            ulonglong2 hA = *(const ulonglong2*)&h_d[k * 4];
            ulonglong2 hB = *(const ulonglong2*)&h_d[k * 4 + 2];
            float2 wp = unpack2(W2p[k * 32 + lane]);
            u64 w0 = dupf(wp.x);
            u64 w1 = dupf(wp.y);
            B00 = ffma2(hA.x, w0, B00);  B01 = ffma2(hA.x, w1, B01);
            B10 = ffma2(hA.y, w0, B10);  B11 = ffma2(hA.y, w1, B11);
            B20 = ffma2(hB.x, w0, B20);  B21 = ffma2(hB.x, w1, B21);
            B30 = ffma2(hB.y, w0, B30);  B31 = ffma2(hB.y, w1, B31);
        }
        {
            u64* p = &psd[ks * 256 + 2 * lane];
            *(ulonglong2*)(p)       = make_ulonglong2(B00, B01);
            *(ulonglong2*)(p + 64)  = make_ulonglong2(B10, B11);
            *(ulonglong2*)(p + 128) = make_ulonglong2(B20, B21);
            *(ulonglong2*)(p + 192) = make_ulonglong2(B30, B31);
        }
        __syncthreads();

        // ---- Epilogue: reduce 16 partials, x update, store states ----
        if (tid < 256) {
            const int rp = rpE, i = iE;
            u64 p[16];
            #pragma unroll
            for (int q = 0; q < 16; ++q) p[q] = psd[q * 256 + rp * 64 + i];
            #pragma unroll
            for (int q = 0; q < 8; ++q) p[q] = fadd2(p[q], p[q + 8]);
            #pragma unroll
            for (int q = 0; q < 4; ++q) p[q] = fadd2(p[q], p[q + 4]);
            p[0] = fadd2(fadd2(p[0], p[2]), fadd2(p[1], p[3]));
            float2 sv = unpack2(p[0]);
            float2 xo = unpack2(in_s[i * 4 + rp]);
            float bb = b2s[i];
            float xn0 = xo.x + DTC * (sv.x + bb);
            float xn1 = xo.y + DTC * (sv.y + bb);
            in_s[i * 4 + rp] = pack2(xn0, xn1);
            size_t obase = (size_t)(t + 1) * SDIM + i;
            out[(size_t)(b0 + 2 * rp) * (TSTEPS + 1) * SDIM + obase]     = xn0;
            out[(size_t)(b0 + 2 * rp + 1) * (TSTEPS + 1) * SDIM + obase] = xn1;
        }
        if (tid < 128 && t + 1 < TSTEPS)
            in_s[(SDIM + lane) * 4 + rpU] = pack2(un0, un1);
        __syncthreads();
    }
}

extern "C" void kernel_launch(void* const* d_in, const int* in_sizes, int n_in,
                              void* d_out, int out_size) {
    const float* x0       = (const float*)d_in[0];
    const float* controls = (const float*)d_in[1];
    const float* W1       = (const float*)d_in[2];
    const float* b1       = (const float*)d_in[3];
    const float* W2       = (const float*)d_in[4];
    const float* b2       = (const float*)d_in[5];
    float* out = (float*)d_out;

    static bool attr_set = false;
    if (!attr_set) {
        cudaFuncSetAttribute(rollout_kernel,
                             cudaFuncAttributeMaxDynamicSharedMemorySize,
                             (int)SMEM_BYTES);
        attr_set = true;
    }
    rollout_kernel<<<NBLK, NTHR, SMEM_BYTES>>>(x0, controls, W1, b1, W2, b2, out);
}